// round 11
// baseline (speedup 1.0000x reference)
#include <cuda_runtime.h>
#include <cstdint>
#include <math.h>

#define TT 64
#define NB 32
#define CC 128
#define DD 64
#define NC (NB * CC)

typedef unsigned long long u64;

// per-(n,c): 64-bit square-model output spike word over t
__device__ u64 g_s2[NC];

// ---------------------------------------------------------------------------
// K1': warp per (n,c) LIF (R7/R10 verified form), then Phase S (square model)
// for the block's 8 channels on warp 0 lanes 0-7. Exact shortcut retained:
// kint>1 + hard reset => integrator spike si_t == (any unit spiked at t).
// ---------------------------------------------------------------------------
__global__ void __launch_bounds__(256) k1_fused(
    const float* __restrict__ x,
    const float* __restrict__ w1, const float* __restrict__ b1,
    const float* __restrict__ w2, const float* __restrict__ b2)
{
    __shared__ u64 sm_siw[8];

    const unsigned FULL = 0xFFFFFFFFu;
    const int tid  = threadIdx.x;
    const int lane = tid & 31;
    const int wid  = tid >> 5;
    const int wg   = blockIdx.x * 8 + wid;   // nc
    const int n = wg >> 7;
    const int c = wg & (CC - 1);

    // pack input spikes: bit t of bx = x[t] != 0
    const int base = n * 2 * CC + c;
    const int strideT = NB * 2 * CC;
    unsigned lo0 = __ballot_sync(FULL, x[base + lane * strideT]             != 0.0f);
    unsigned hi0 = __ballot_sync(FULL, x[base + (lane + 32) * strideT]      != 0.0f);
    unsigned lo1 = __ballot_sync(FULL, x[base + CC + lane * strideT]        != 0.0f);
    unsigned hi1 = __ballot_sync(FULL, x[base + CC + (lane + 32) * strideT] != 0.0f);
    u64 bx0 = (u64)lo0 | ((u64)hi0 << 32);
    u64 bx1 = (u64)lo1 | ((u64)hi1 << 32);

    // unit j sees x0 delayed by j, x1 delayed by (D-1-j): pre-shift
    u64 a0 = bx0 << lane;            // unit j0 = lane
    u64 a1 = bx0 << (lane + 32);     // unit j1 = lane + 32
    u64 d0 = bx1 << (63 - lane);
    u64 d1 = bx1 << (31 - lane);

    float vj0 = 0.0f, vj1 = 0.0f;
    u64 siw = 0ull;

    #pragma unroll
    for (int t = 0; t < TT; ++t) {
        float u0 = (((a0 >> t) & 1ull) ? 1.0f : 0.0f)
                 + (((d0 >> t) & 1ull) ? 1.0f : 0.0f);
        float u1 = (((a1 >> t) & 1ull) ? 1.0f : 0.0f)
                 + (((d1 >> t) & 1ull) ? 1.0f : 0.0f);
        vj0 = fmaf(u0 - vj0, 0.05f, vj0);
        vj1 = fmaf(u1 - vj1, 0.05f, vj1);
        bool s0 = (vj0 >= 1.0f), s1 = (vj1 >= 1.0f);
        bool any = __any_sync(FULL, s0 | s1);
        vj0 = s0 ? 0.0f : vj0;
        vj1 = s1 ? 0.0f : vj1;
        siw |= any ? (1ull << t) : 0ull;
    }

    if (lane == 0) sm_siw[wid] = siw;   // siw uniform across lanes (VOTE)
    __syncthreads();

    // ---- Phase S: square model for the block's 8 channels, warp 0 only.
    //      Lane l < 8 owns channel blockIdx*8 + l (lanes 8-31 compute
    //      replicas of lane l&7 and are masked at the store). ----
    if (wid == 0) {
        const u64 s = sm_siw[lane & 7];

        float w1r[10], b1r[10], w2r[10];
        #pragma unroll
        for (int i = 0; i < 10; ++i) { w1r[i] = w1[i]; b1r[i] = b1[i]; w2r[i] = w2[i]; }
        const float b2v = b2[0];
        float babs = fabsf(b2v);
        #pragma unroll
        for (int i = 0; i < 10; ++i) babs += fabsf(b1r[i]);
        const bool bias_zero = (babs == 0.0f);   // warp-uniform

        float f1 = 0.0f, dotp = 0.0f, v2 = 0.0f;
        float v1[10];
        #pragma unroll
        for (int i = 0; i < 10; ++i) v1[i] = 0.0f;
        u64 s2w = 0ull;

        if (bias_zero) {
            // exact: x + 0.0f == x for every value arising here
            #pragma unroll 4
            for (int t = 0; t < TT; ++t) {
                float sif = ((s >> t) & 1ull) ? 1.0f : 0.0f;
                f1 = fmaf(f1, 0.5f, sif);
                float nv[10], cv[10];
                bool  sq[10];
                #pragma unroll
                for (int i = 0; i < 10; ++i) nv[i] = fmaf(f1, w1r[i], v1[i]);
                #pragma unroll
                for (int i = 0; i < 10; ++i) sq[i] = (nv[i] >= 1.0f);
                #pragma unroll
                for (int i = 0; i < 10; ++i) v1[i] = sq[i] ? 0.0f : nv[i];
                #pragma unroll
                for (int i = 0; i < 10; ++i) cv[i] = sq[i] ? w2r[i] : 0.0f;
                float s01 = cv[0] + cv[1], s23 = cv[2] + cv[3];
                float s45 = cv[4] + cv[5], s67 = cv[6] + cv[7];
                float s89 = cv[8] + cv[9];
                float dsum = ((s01 + s23) + (s45 + s67)) + s89;
                dotp = fmaf(dotp, 0.5f, dsum);      // = w2 . f2_t
                v2 += dotp;
                bool s2 = (v2 >= 1.0f);
                v2 = s2 ? 0.0f : v2;
                s2w |= s2 ? (1ull << t) : 0ull;
            }
        } else {
            #pragma unroll 4
            for (int t = 0; t < TT; ++t) {
                float sif = ((s >> t) & 1ull) ? 1.0f : 0.0f;
                f1 = fmaf(f1, 0.5f, sif);
                float nv[10], cv[10];
                bool  sq[10];
                #pragma unroll
                for (int i = 0; i < 10; ++i) nv[i] = fmaf(f1, w1r[i], v1[i]) + b1r[i];
                #pragma unroll
                for (int i = 0; i < 10; ++i) sq[i] = (nv[i] >= 1.0f);
                #pragma unroll
                for (int i = 0; i < 10; ++i) v1[i] = sq[i] ? 0.0f : nv[i];
                #pragma unroll
                for (int i = 0; i < 10; ++i) cv[i] = sq[i] ? w2r[i] : 0.0f;
                float s01 = cv[0] + cv[1], s23 = cv[2] + cv[3];
                float s45 = cv[4] + cv[5], s67 = cv[6] + cv[7];
                float s89 = cv[8] + cv[9];
                float dsum = ((s01 + s23) + (s45 + s67)) + s89;
                dotp = fmaf(dotp, 0.5f, dsum);
                v2 += dotp + b2v;
                bool s2 = (v2 >= 1.0f);
                v2 = s2 ? 0.0f : v2;
                s2w |= s2 ? (1ull << t) : 0ull;
            }
        }

        if (lane < 8) g_s2[blockIdx.x * 8 + lane] = s2w;
    }
}

// ---------------------------------------------------------------------------
// K_TAIL: one block per n, 128 threads. Phased tail (verified R4/R5/R10 code):
//  P1 spike counts -> P2 serial h/q0 (reg-prefetched counts) ->
//  P3 t-parallel masked matvec -> P4 serial chain (reg-prefetched msb) ->
//  P5 reduce q2 partials.
// ---------------------------------------------------------------------------
__global__ void __launch_bounds__(128) k_tail(
    const float* __restrict__ sw0, const float* __restrict__ sb0,
    const float* __restrict__ sw1, const float* __restrict__ sb1,
    const float* __restrict__ sw2, const float* __restrict__ sb2,
    float* __restrict__ out)
{
    __shared__ u64 words[CC];
    __shared__ float sw1s[32 * 33];
    __shared__ int   cnt2[128];
    __shared__ float cntf[TT];
    __shared__ unsigned sa_masks[TT];
    __shared__ float msb[TT][33];
    __shared__ float qbuf[TT][33];

    const unsigned FULL = 0xFFFFFFFFu;
    const int n = blockIdx.x;
    const int tid = threadIdx.x;
    const int lane = tid & 31;
    const int wid = tid >> 5;

    words[tid] = g_s2[n * CC + tid];
    #pragma unroll
    for (int i = tid; i < 1024; i += 128) {
        int row = i >> 5, col = i & 31;
        sw1s[row * 33 + col] = sw1[i];
    }
    __syncthreads();

    // ---- P1: spike count over c per timestep (2 threads per t) ----
    {
        int t = tid >> 1, h = tid & 1;
        int cnt = 0;
        #pragma unroll 8
        for (int cc = 0; cc < 64; ++cc)
            cnt += (int)((words[h * 64 + cc] >> t) & 1ull);
        cnt2[tid] = cnt;
    }
    float r[32];
    #pragma unroll
    for (int k = 0; k < 32; ++k) r[k] = sw1s[lane * 33 + k];
    __syncthreads();
    if (tid < 64) cntf[tid] = (float)(cnt2[2 * tid] + cnt2[2 * tid + 1]);
    __syncthreads();

    // ---- P2: serial h + q0 chain -> sA masks (counts prefetched to regs) ----
    if (wid == 0) {
        const float sw0l = sw0[lane], sb0l = sb0[lane];
        float fsum = 0.0f, vs = 0.0f, q0 = 0.0f;
        #pragma unroll 1
        for (int cch = 0; cch < 4; ++cch) {
            float cf[16];
            #pragma unroll
            for (int tt = 0; tt < 16; ++tt)
                cf[tt] = cntf[16 * cch + tt];             // pipelined, off-chain
            #pragma unroll
            for (int tt = 0; tt < 16; ++tt) {
                int t = 16 * cch + tt;
                fsum = fmaf(fsum, 0.5f, cf[tt]);
                vs += fsum;
                bool s5 = (vs >= 1.0f);
                float hf = s5 ? 1.0f : 0.0f;
                vs = s5 ? 0.0f : vs;
                q0 += fmaf(hf, sw0l, sb0l);
                bool pA = (q0 >= 1.0f);
                unsigned m = __ballot_sync(FULL, pA);
                q0 = pA ? 0.0f : q0;
                if (lane == 0) sa_masks[t] = m;
            }
        }
    }
    __syncthreads();

    // ---- P3: t-parallel masked row sums (16 timesteps per warp) ----
    {
        const int t0 = wid * 16;
        #pragma unroll
        for (int t = t0; t < t0 + 16; ++t) {
            unsigned m = sa_masks[t];
            float a0 = 0.0f, a1 = 0.0f, a2 = 0.0f, a3 = 0.0f;
            #pragma unroll
            for (int k = 0; k < 32; k += 4) {
                if (m & (1u << k))       a0 += r[k];
                if (m & (1u << (k + 1))) a1 += r[k + 1];
                if (m & (1u << (k + 2))) a2 += r[k + 2];
                if (m & (1u << (k + 3))) a3 += r[k + 3];
            }
            msb[t][lane] = (a0 + a1) + (a2 + a3);
        }
    }
    __syncthreads();

    // ---- P4: serial dot/q1/g2/q2 chain (msb prefetched per chunk) ----
    if (wid == 0) {
        const float sb1l = sb1[lane], sw2l = sw2[lane];
        const float sb2v = (lane == 0) ? sb2[0] : 0.0f;
        float dot = 0.0f, q1 = 0.0f, g2 = 0.0f, q2p = 0.0f;
        #pragma unroll 1
        for (int cch = 0; cch < 4; ++cch) {
            float mv[16];
            #pragma unroll
            for (int tt = 0; tt < 16; ++tt)
                mv[tt] = msb[16 * cch + tt][lane];        // pipelined, off-chain
            #pragma unroll
            for (int tt = 0; tt < 16; ++tt) {
                int t = 16 * cch + tt;
                dot = fmaf(dot, 0.5f, mv[tt]);   // = sw1 . g1_t
                q1 = q1 + dot + sb1l;
                bool pB = (q1 >= 1.0f);
                float sBf = pB ? 1.0f : 0.0f;
                q1 = pB ? 0.0f : q1;
                g2 = fmaf(g2, 0.5f, sBf);
                q2p = fmaf(g2, sw2l, q2p) + sb2v;
                qbuf[t][lane] = q2p;
            }
        }
    }
    __syncthreads();

    // ---- P5: reduce per-lane q2 partials -> out (T,N,1) ----
    if (tid < 64) {
        int t = tid;
        float s = 0.0f;
        #pragma unroll
        for (int l = 0; l < 32; ++l) s += qbuf[t][l];
        out[t * NB + n] = s;
    }
}

// ---------------------------------------------------------------------------
extern "C" void kernel_launch(void* const* d_in, const int* in_sizes, int n_in,
                              void* d_out, int out_size)
{
    const float* x   = (const float*)d_in[0];
    const float* w1  = (const float*)d_in[1];
    const float* b1  = (const float*)d_in[2];
    const float* w2  = (const float*)d_in[3];
    const float* b2  = (const float*)d_in[4];
    const float* sw0 = (const float*)d_in[5];
    const float* sb0 = (const float*)d_in[6];
    const float* sw1 = (const float*)d_in[7];
    const float* sb1 = (const float*)d_in[8];
    const float* sw2 = (const float*)d_in[9];
    const float* sb2 = (const float*)d_in[10];
    float* out = (float*)d_out;

    k1_fused<<<512, 256>>>(x, w1, b1, w2, b2);
    k_tail<<<NB, 128>>>(sw0, sb0, sw1, sb1, sw2, sb2, out);
}

// round 12
// speedup vs baseline: 1.0455x; 1.0455x over previous
#include <cuda_runtime.h>
#include <cstdint>
#include <math.h>

#define TT 64
#define NB 32
#define CC 128
#define DD 64
#define NC (NB * CC)

typedef unsigned long long u64;

// per-(n,c): 64-bit integrator-spike word over t (si = any jeffress spike)
__device__ u64 g_si[NC];
// per-n producer-completion counter (zero-initialized; consumer restores 0)
__device__ int g_done[NB];

// ---------------------------------------------------------------------------
// Single fused kernel, grid = NB + 512 blocks x 256 threads.
//   blocks 0..31    : consumer for n = blockIdx (prefetch, spin, PhaseS+tail)
//   blocks 32..543  : producer pid = blockIdx-32, warp per (n,c) LIF
// Exact shortcut retained: kint>1 + hard reset => integrator spike si_t ==
// (any jeffress unit spiked at t).
// ---------------------------------------------------------------------------
__global__ void __launch_bounds__(256, 2) fused_all(
    const float* __restrict__ x,
    const float* __restrict__ w1, const float* __restrict__ b1,
    const float* __restrict__ w2, const float* __restrict__ b2,
    const float* __restrict__ sw0, const float* __restrict__ sb0,
    const float* __restrict__ sw1, const float* __restrict__ sb1,
    const float* __restrict__ sw2, const float* __restrict__ sb2,
    float* __restrict__ out)
{
    __shared__ u64 words[CC];
    __shared__ float sw1s[32 * 33];
    __shared__ int   cnt2[128];
    __shared__ float cntf[TT];
    __shared__ unsigned sa_masks[TT];
    __shared__ float msb[TT][33];
    __shared__ float qbuf[TT][33];

    const unsigned FULL = 0xFFFFFFFFu;
    const int tid  = threadIdx.x;
    const int lane = tid & 31;
    const int wid  = tid >> 5;

    if (blockIdx.x >= NB) {
        // =================== PRODUCER: LIF for 8 (n,c) ===================
        const int pid = blockIdx.x - NB;
        const int wg  = pid * 8 + wid;       // nc
        const int n = wg >> 7;
        const int c = wg & (CC - 1);

        const int base = n * 2 * CC + c;
        const int strideT = NB * 2 * CC;
        unsigned lo0 = __ballot_sync(FULL, x[base + lane * strideT]             != 0.0f);
        unsigned hi0 = __ballot_sync(FULL, x[base + (lane + 32) * strideT]      != 0.0f);
        unsigned lo1 = __ballot_sync(FULL, x[base + CC + lane * strideT]        != 0.0f);
        unsigned hi1 = __ballot_sync(FULL, x[base + CC + (lane + 32) * strideT] != 0.0f);
        u64 bx0 = (u64)lo0 | ((u64)hi0 << 32);
        u64 bx1 = (u64)lo1 | ((u64)hi1 << 32);

        u64 a0 = bx0 << lane;            // unit j0 = lane
        u64 a1 = bx0 << (lane + 32);     // unit j1 = lane + 32
        u64 d0 = bx1 << (63 - lane);
        u64 d1 = bx1 << (31 - lane);

        float vj0 = 0.0f, vj1 = 0.0f;
        u64 siw = 0ull;

        #pragma unroll
        for (int t = 0; t < TT; ++t) {
            float u0 = (((a0 >> t) & 1ull) ? 1.0f : 0.0f)
                     + (((d0 >> t) & 1ull) ? 1.0f : 0.0f);
            float u1 = (((a1 >> t) & 1ull) ? 1.0f : 0.0f)
                     + (((d1 >> t) & 1ull) ? 1.0f : 0.0f);
            vj0 = fmaf(u0 - vj0, 0.05f, vj0);
            vj1 = fmaf(u1 - vj1, 0.05f, vj1);
            bool s0 = (vj0 >= 1.0f), s1 = (vj1 >= 1.0f);
            bool any = __any_sync(FULL, s0 | s1);
            vj0 = s0 ? 0.0f : vj0;
            vj1 = s1 ? 0.0f : vj1;
            siw |= any ? (1ull << t) : 0ull;
        }

        if (lane == 0) g_si[wg] = siw;
        __threadfence();
        __syncthreads();
        if (tid == 0) atomicAdd(&g_done[pid >> 4], 1);
        return;
    }

    // ====================== CONSUMER for n = blockIdx ======================
    const int n = blockIdx.x;

    // prologue loads (independent of producers — hidden under the spin)
    #pragma unroll
    for (int i = tid; i < 1024; i += 256) {
        int row = i >> 5, col = i & 31;
        sw1s[row * 33 + col] = sw1[i];
    }
    float w1r[10], b1r[10], w2r[10];
    float b2v = 0.0f;
    bool bias_zero = true;
    if (tid < 128) {
        #pragma unroll
        for (int i = 0; i < 10; ++i) { w1r[i] = w1[i]; b1r[i] = b1[i]; w2r[i] = w2[i]; }
        b2v = b2[0];
        float babs = fabsf(b2v);
        #pragma unroll
        for (int i = 0; i < 10; ++i) babs += fabsf(b1r[i]);
        bias_zero = (babs == 0.0f);          // uniform across tid<128
    }

    // wait for this n's 16 producers; restore counter for the next replay
    if (tid == 0) {
        while (atomicAdd(&g_done[n], 0) < 16) __nanosleep(64);
        atomicSub(&g_done[n], 16);
        __threadfence();
    }
    __syncthreads();

    // ---- Phase S: square model per channel (tid = channel, tid<128) ----
    if (tid < 128) {
        const u64 siw = g_si[n * CC + tid];
        float f1 = 0.0f, dotp = 0.0f, v2 = 0.0f;
        float v1[10];
        #pragma unroll
        for (int i = 0; i < 10; ++i) v1[i] = 0.0f;
        u64 s2w = 0ull;

        if (bias_zero) {
            // exact: x + 0.0f == x for every value arising here
            #pragma unroll 4
            for (int t = 0; t < TT; ++t) {
                float sif = ((siw >> t) & 1ull) ? 1.0f : 0.0f;
                f1 = fmaf(f1, 0.5f, sif);
                float nv[10], cv[10];
                bool  sq[10];
                #pragma unroll
                for (int i = 0; i < 10; ++i) nv[i] = fmaf(f1, w1r[i], v1[i]);
                #pragma unroll
                for (int i = 0; i < 10; ++i) sq[i] = (nv[i] >= 1.0f);
                #pragma unroll
                for (int i = 0; i < 10; ++i) v1[i] = sq[i] ? 0.0f : nv[i];
                #pragma unroll
                for (int i = 0; i < 10; ++i) cv[i] = sq[i] ? w2r[i] : 0.0f;
                float s01 = cv[0] + cv[1], s23 = cv[2] + cv[3];
                float s45 = cv[4] + cv[5], s67 = cv[6] + cv[7];
                float s89 = cv[8] + cv[9];
                float dsum = ((s01 + s23) + (s45 + s67)) + s89;
                dotp = fmaf(dotp, 0.5f, dsum);      // = w2 . f2_t
                v2 += dotp;
                bool s2 = (v2 >= 1.0f);
                v2 = s2 ? 0.0f : v2;
                s2w |= s2 ? (1ull << t) : 0ull;
            }
        } else {
            #pragma unroll 4
            for (int t = 0; t < TT; ++t) {
                float sif = ((siw >> t) & 1ull) ? 1.0f : 0.0f;
                f1 = fmaf(f1, 0.5f, sif);
                float nv[10], cv[10];
                bool  sq[10];
                #pragma unroll
                for (int i = 0; i < 10; ++i) nv[i] = fmaf(f1, w1r[i], v1[i]) + b1r[i];
                #pragma unroll
                for (int i = 0; i < 10; ++i) sq[i] = (nv[i] >= 1.0f);
                #pragma unroll
                for (int i = 0; i < 10; ++i) v1[i] = sq[i] ? 0.0f : nv[i];
                #pragma unroll
                for (int i = 0; i < 10; ++i) cv[i] = sq[i] ? w2r[i] : 0.0f;
                float s01 = cv[0] + cv[1], s23 = cv[2] + cv[3];
                float s45 = cv[4] + cv[5], s67 = cv[6] + cv[7];
                float s89 = cv[8] + cv[9];
                float dsum = ((s01 + s23) + (s45 + s67)) + s89;
                dotp = fmaf(dotp, 0.5f, dsum);
                v2 += dotp + b2v;
                bool s2 = (v2 >= 1.0f);
                v2 = s2 ? 0.0f : v2;
                s2w |= s2 ? (1ull << t) : 0ull;
            }
        }
        words[tid] = s2w;
    }
    __syncthreads();

    // ---- P1: spike count over c per timestep (2 threads per t) ----
    if (tid < 128) {
        int t = tid >> 1, h = tid & 1;
        int cnt = 0;
        #pragma unroll 8
        for (int cc = 0; cc < 64; ++cc)
            cnt += (int)((words[h * 64 + cc] >> t) & 1ull);
        cnt2[tid] = cnt;
    }
    float r[32];
    #pragma unroll
    for (int k = 0; k < 32; ++k) r[k] = sw1s[lane * 33 + k];
    __syncthreads();
    if (tid < 64) cntf[tid] = (float)(cnt2[2 * tid] + cnt2[2 * tid + 1]);
    __syncthreads();

    // ---- P2: serial h + q0 chain -> sA masks (counts prefetched to regs) ----
    if (wid == 0) {
        const float sw0l = sw0[lane], sb0l = sb0[lane];
        float fsum = 0.0f, vs = 0.0f, q0 = 0.0f;
        #pragma unroll 1
        for (int cch = 0; cch < 4; ++cch) {
            float cf[16];
            #pragma unroll
            for (int tt = 0; tt < 16; ++tt)
                cf[tt] = cntf[16 * cch + tt];             // off-chain
            #pragma unroll
            for (int tt = 0; tt < 16; ++tt) {
                int t = 16 * cch + tt;
                fsum = fmaf(fsum, 0.5f, cf[tt]);
                vs += fsum;
                bool s5 = (vs >= 1.0f);
                float hf = s5 ? 1.0f : 0.0f;
                vs = s5 ? 0.0f : vs;
                q0 += fmaf(hf, sw0l, sb0l);
                bool pA = (q0 >= 1.0f);
                unsigned m = __ballot_sync(FULL, pA);
                q0 = pA ? 0.0f : q0;
                if (lane == 0) sa_masks[t] = m;
            }
        }
    }
    __syncthreads();

    // ---- P3: t-parallel masked row sums (16 timesteps per warp, wid<4) ----
    if (wid < 4) {
        const int t0 = wid * 16;
        #pragma unroll
        for (int t = t0; t < t0 + 16; ++t) {
            unsigned m = sa_masks[t];
            float a0 = 0.0f, a1 = 0.0f, a2 = 0.0f, a3 = 0.0f;
            #pragma unroll
            for (int k = 0; k < 32; k += 4) {
                if (m & (1u << k))       a0 += r[k];
                if (m & (1u << (k + 1))) a1 += r[k + 1];
                if (m & (1u << (k + 2))) a2 += r[k + 2];
                if (m & (1u << (k + 3))) a3 += r[k + 3];
            }
            msb[t][lane] = (a0 + a1) + (a2 + a3);
        }
    }
    __syncthreads();

    // ---- P4: serial dot/q1/g2/q2 chain (msb prefetched per chunk) ----
    if (wid == 0) {
        const float sb1l = sb1[lane], sw2l = sw2[lane];
        const float sb2v = (lane == 0) ? sb2[0] : 0.0f;
        float dot = 0.0f, q1 = 0.0f, g2 = 0.0f, q2p = 0.0f;
        #pragma unroll 1
        for (int cch = 0; cch < 4; ++cch) {
            float mv[16];
            #pragma unroll
            for (int tt = 0; tt < 16; ++tt)
                mv[tt] = msb[16 * cch + tt][lane];        // off-chain
            #pragma unroll
            for (int tt = 0; tt < 16; ++tt) {
                int t = 16 * cch + tt;
                dot = fmaf(dot, 0.5f, mv[tt]);   // = sw1 . g1_t
                q1 = q1 + dot + sb1l;
                bool pB = (q1 >= 1.0f);
                float sBf = pB ? 1.0f : 0.0f;
                q1 = pB ? 0.0f : q1;
                g2 = fmaf(g2, 0.5f, sBf);
                q2p = fmaf(g2, sw2l, q2p) + sb2v;
                qbuf[t][lane] = q2p;
            }
        }
    }
    __syncthreads();

    // ---- P5: reduce per-lane q2 partials -> out (T,N,1) ----
    if (tid < 64) {
        int t = tid;
        float s = 0.0f;
        #pragma unroll
        for (int l = 0; l < 32; ++l) s += qbuf[t][l];
        out[t * NB + n] = s;
    }
}

// ---------------------------------------------------------------------------
extern "C" void kernel_launch(void* const* d_in, const int* in_sizes, int n_in,
                              void* d_out, int out_size)
{
    const float* x   = (const float*)d_in[0];
    const float* w1  = (const float*)d_in[1];
    const float* b1  = (const float*)d_in[2];
    const float* w2  = (const float*)d_in[3];
    const float* b2  = (const float*)d_in[4];
    const float* sw0 = (const float*)d_in[5];
    const float* sb0 = (const float*)d_in[6];
    const float* sw1 = (const float*)d_in[7];
    const float* sb1 = (const float*)d_in[8];
    const float* sw2 = (const float*)d_in[9];
    const float* sb2 = (const float*)d_in[10];
    float* out = (float*)d_out;

    fused_all<<<NB + 512, 256>>>(x, w1, b1, w2, b2,
                                 sw0, sb0, sw1, sb1, sw2, sb2, out);
}